// round 17
// baseline (speedup 1.0000x reference)
#include <cuda_runtime.h>
#include <cuda_fp16.h>
#include <cstdint>

#define T_   128
#define B_   64
#define E_   300
#define H_   2048
#define G4   8192
#define TB   8192
#define KP   320
#define KCAT 960

// step-kernel config: two K-groups x 4 warps, K32 chunks, 4 stages,
// 2 chunks per round (16 rounds), prefetch distance 2 rounds.
#define NCTA    128
#define NT      64                // gate rows per CTA
#define JT      16                // hidden units per CTA
#define ROWB    80                // padded row stride (64B data + 16B pad)
#define A_ST    10240             // 128 rows x 80B
#define B_ST    5120              // 64 rows x 80B
#define STAGE_B (A_ST + B_ST)     // 15360
#define NSTG    4
#define GRP_SMEM (NSTG * STAGE_B) // 61440 per group
#define DYN_SMEM (2 * GRP_SMEM)   // 122880
#define KHALF   1024
#define NCHUNK  32                // K32 chunks per K-half

// ---------------- scratch ----------------
__device__ __align__(256) __half g_Acat[(size_t)TB * KCAT];
__device__ __align__(256) __half g_Bcat[(size_t)G4 * KCAT];
__device__ __align__(256) __half g_Whh16[(size_t)G4 * H_];   // gate-interleaved rows
__device__ __align__(256) float  g_Xg[(size_t)TB * G4];      // [t*B+b][np] np=4j+g
__device__ __align__(256) float  g_bias[G4];
__device__ __align__(256) float  g_c[128 * H_];              // cell state
__device__ __align__(256) __half g_h16[128 * H_];            // hidden state

// ---------------- helpers ----------------
__device__ __forceinline__ uint32_t smemAddr(const void* p) {
    return (uint32_t)__cvta_generic_to_shared(p);
}
__device__ __forceinline__ void ldsm4(uint32_t r[4], uint32_t addr) {
    asm volatile("ldmatrix.sync.aligned.m8n8.x4.shared.b16 {%0,%1,%2,%3}, [%4];\n"
                 : "=r"(r[0]), "=r"(r[1]), "=r"(r[2]), "=r"(r[3]) : "r"(addr));
}
__device__ __forceinline__ void mma16816(float* c, const uint32_t* a, const uint32_t* b) {
    asm volatile("mma.sync.aligned.m16n8k16.row.col.f32.f16.f16.f32 "
                 "{%0,%1,%2,%3}, {%4,%5,%6,%7}, {%8,%9}, {%0,%1,%2,%3};\n"
                 : "+f"(c[0]), "+f"(c[1]), "+f"(c[2]), "+f"(c[3])
                 : "r"(a[0]), "r"(a[1]), "r"(a[2]), "r"(a[3]), "r"(b[0]), "r"(b[1]));
}
#define CP16(dst, src) asm volatile("cp.async.cg.shared.global [%0], [%1], 16;\n" :: "r"(dst), "l"(src))
#define CP_COMMIT()    asm volatile("cp.async.commit_group;\n" ::: "memory")
#define CP_WAIT(N)     asm volatile("cp.async.wait_group %0;\n" :: "n"(N) : "memory")
#define BARG(id)       asm volatile("bar.sync %0, %1;" :: "r"(id), "r"(128) : "memory")

__device__ __forceinline__ float sigm(float x) { return 1.f / (1.f + __expf(-x)); }
__device__ __forceinline__ float tanh_f(float x) { return 2.f / (1.f + __expf(-2.f * x)) - 1.f; }

// ---------------- merged prep kernel (block-range dispatch) ----------------
#define NB_WHH  65536     // G4*H/256
#define NB_WIH  10240     // G4*KP/256
#define NB_X    10240     // TB*KP/256
#define NB_MISC 1056      // 1024 (state) + 32 (bias)
__global__ void prep_all(const int* __restrict__ tokens, const float* __restrict__ embed,
                         const float* __restrict__ W_ih, const float* __restrict__ W_hh,
                         const float* __restrict__ b_ih, const float* __restrict__ b_hh)
{
    int blk = blockIdx.x;
    if (blk < NB_WHH) {
        int i = blk * 256 + threadIdx.x;
        int n = i >> 11, k = i & (H_ - 1);
        int np = ((n & (H_ - 1)) << 2) | (n >> 11);
        g_Whh16[(size_t)np * H_ + k] = __float2half(W_hh[i]);
        return;
    }
    blk -= NB_WHH;
    if (blk < NB_WIH) {
        int i = blk * 256 + threadIdx.x;
        int n = i / KP, c = i % KP;
        int np = ((n & (H_ - 1)) << 2) | (n >> 11);
        float w = (c < E_) ? W_ih[n * E_ + c] : 0.f;
        __half hi = __float2half(w);
        __half lo = __float2half(w - __half2float(hi));
        g_Bcat[(size_t)np * KCAT + c]          = hi;
        g_Bcat[(size_t)np * KCAT + KP + c]     = lo;
        g_Bcat[(size_t)np * KCAT + 2 * KP + c] = hi;
        return;
    }
    blk -= NB_WIH;
    if (blk < NB_X) {
        int i = blk * 256 + threadIdx.x;
        int row = i / KP, c = i % KP;
        int tok = tokens[row];
        float v = (c < E_) ? embed[(size_t)tok * E_ + c] : 0.f;
        __half hi = __float2half(v);
        __half lo = __float2half(v - __half2float(hi));
        g_Acat[(size_t)row * KCAT + c]          = hi;
        g_Acat[(size_t)row * KCAT + KP + c]     = hi;
        g_Acat[(size_t)row * KCAT + 2 * KP + c] = lo;
        return;
    }
    blk -= NB_X;
    if (blk < 1024) {
        int i = blk * 256 + threadIdx.x;
        g_c[i] = 0.f;
        g_h16[i] = __float2half(0.f);
        return;
    }
    blk -= 1024;
    {
        int i = blk * 256 + threadIdx.x;
        if (i < G4) g_bias[i] = b_ih[i] + b_hh[i];
    }
}

// ---------------- Xg GEMM (C[M,N]=A@B^T, tile 128x64, runs once) ----------------
__global__ __launch_bounds__(256) void gemm_kernel(
    const __half* __restrict__ A, const __half* __restrict__ B, float* __restrict__ C,
    int lda, int ldb, int ldc, int K)
{
    __shared__ __half As[128][72];
    __shared__ __half Bs[64][72];
    int tid = threadIdx.x, lane = tid & 31, warp = tid >> 5;
    int wm = warp & 3, wn = warp >> 2;
    int m0 = blockIdx.y * 128, n0 = blockIdx.x * 64;

    float acc[2][4][4];
#pragma unroll
    for (int mi = 0; mi < 2; mi++)
#pragma unroll
        for (int ni = 0; ni < 4; ni++)
#pragma unroll
            for (int q = 0; q < 4; q++) acc[mi][ni][q] = 0.f;

    uint32_t asB = smemAddr(As), bsB = smemAddr(Bs);
    uint32_t aRowByte = (uint32_t)(wm * 32 + (lane & 15)) * 144;
    uint32_t aColByte = (uint32_t)((lane >> 4) << 3) * 2;
    uint32_t bRowByte = (uint32_t)(wn * 32 + ((lane >> 4) & 1) * 8 + (lane & 7)) * 144;
    uint32_t bColByte = (uint32_t)(((lane >> 3) & 1) << 3) * 2;

    for (int k0 = 0; k0 < K; k0 += 64) {
#pragma unroll
        for (int i = 0; i < 4; i++) {
            int v = tid + i * 256; int r = v >> 3, cc = (v & 7) << 3;
            *(uint4*)&As[r][cc] = *(const uint4*)&A[(size_t)(m0 + r) * lda + k0 + cc];
        }
#pragma unroll
        for (int i = 0; i < 2; i++) {
            int v = tid + i * 256; int r = v >> 3, cc = (v & 7) << 3;
            *(uint4*)&Bs[r][cc] = *(const uint4*)&B[(size_t)(n0 + r) * ldb + k0 + cc];
        }
        __syncthreads();
#pragma unroll
        for (int ks = 0; ks < 4; ks++) {
            uint32_t a[2][4], b[2][4];
            uint32_t ka = (uint32_t)ks * 32;
            ldsm4(a[0], asB + aRowByte + ka + aColByte);
            ldsm4(a[1], asB + aRowByte + 16u * 144 + ka + aColByte);
            ldsm4(b[0], bsB + bRowByte + ka + bColByte);
            ldsm4(b[1], bsB + bRowByte + 16u * 144 + ka + bColByte);
#pragma unroll
            for (int mi = 0; mi < 2; mi++)
#pragma unroll
                for (int ni = 0; ni < 4; ni++)
                    mma16816(acc[mi][ni], a[mi], &b[ni >> 1][(ni & 1) * 2]);
        }
        __syncthreads();
    }
#pragma unroll
    for (int mi = 0; mi < 2; mi++) {
        int row = m0 + wm * 32 + mi * 16 + (lane >> 2);
#pragma unroll
        for (int ni = 0; ni < 4; ni++) {
            int col = n0 + wn * 32 + ni * 8 + ((lane & 3) << 1);
            float* cp = C + (size_t)row * ldc + col;
            cp[0] = acc[mi][ni][0]; cp[1] = acc[mi][ni][1];
            cp += (size_t)ldc * 8;
            cp[0] = acc[mi][ni][2]; cp[1] = acc[mi][ni][3];
        }
    }
}

// ---------------- fused LSTM step kernel ----------------
// 128 CTAs x 256 thr. Warps 0-3 = group 0 (K[0,1024)), warps 4-7 = group 1.
// 4 stages of K32; 2 chunks per round: WAIT -> BARG -> ldsm(2) -> BARG ->
// commit(2 chunks, distance 2 rounds) -> 64 mmas.
__global__ __launch_bounds__(256, 1) void lstm_step(
    int s, const int* __restrict__ lens, float* __restrict__ out)
{
    extern __shared__ char dsm[];
    __shared__ float Cs[128][68];
    __shared__ float sBias[NT];

    const int tid = threadIdx.x, lane = tid & 31;
    const int g    = tid >> 7;           // K-group 0/1
    const int gtid = tid & 127;
    const int gwarp = gtid >> 5;         // 0..3 within group
    const int wm = gwarp & 1;            // 2 along M (64 rows each)
    const int wn = gwarp >> 1;           // 2 along N (32 cols each)
    const int cta = blockIdx.x;
    const int n0 = cta * NT;
    const int j0 = cta * JT;
    const int barId = 1 + g;

    const uint32_t stB = smemAddr(dsm) + (uint32_t)g * GRP_SMEM;

    if (tid < NT) sBias[tid] = g_bias[(tid & 3) * H_ + j0 + (tid >> 2)];

    // loader offsets (per group, 128 threads): A 4 units/thr, B 2 units/thr
    uint32_t aDst[4]; const __half* aSrc[4];
#pragma unroll
    for (int i = 0; i < 4; i++) {
        int v = gtid + i * 128, r = v >> 2, sg = v & 3;
        aDst[i] = (uint32_t)(r * ROWB + sg * 16);
        aSrc[i] = g_h16 + (size_t)r * H_ + g * KHALF + sg * 8;
    }
    uint32_t bDst[2]; const __half* bSrc[2];
#pragma unroll
    for (int i = 0; i < 2; i++) {
        int v = gtid + i * 128, r = v >> 2, sg = v & 3;
        bDst[i] = (uint32_t)(A_ST + r * ROWB + sg * 16);
        bSrc[i] = g_Whh16 + (size_t)(n0 + r) * H_ + g * KHALF + sg * 8;
    }

    // ldsm addressing within a stage
    const uint32_t aRowByte = (uint32_t)(wm * 64 + (lane & 15)) * ROWB;
    const uint32_t aColByte = (uint32_t)((lane >> 4) << 4);
    const uint32_t bRowByte = (uint32_t)(wn * 32 + ((lane >> 4) & 1) * 8 + (lane & 7)) * ROWB;
    const uint32_t bColByte = (uint32_t)(((lane >> 3) & 1) << 4);

    float acc[4][4][4];    // [mi][ni][q], warp tile 64x32
#pragma unroll
    for (int mi = 0; mi < 4; mi++)
#pragma unroll
        for (int ni = 0; ni < 4; ni++)
#pragma unroll
            for (int q = 0; q < 4; q++) acc[mi][ni][q] = 0.f;

    // prologue: chunks 0..3 -> stages 0..3 (4 commits)
#pragma unroll
    for (int p = 0; p < 4; p++) {
        uint32_t base = stB + (uint32_t)p * STAGE_B;
#pragma unroll
        for (int i = 0; i < 4; i++) CP16(base + aDst[i], aSrc[i] + p * 32);
#pragma unroll
        for (int i = 0; i < 2; i++) CP16(base + bDst[i], bSrc[i] + p * 32);
        CP_COMMIT();
    }

    // -------- mainloop: 16 rounds x 2 chunks --------
    for (int r = 0; r < 16; r++) {
        const int c0 = 2 * r;
        if (r < 15) CP_WAIT(2); else CP_WAIT(0);
        BARG(barId);                       // all threads' waits done -> data valid

        uint32_t base0 = stB + (uint32_t)(c0 & 3) * STAGE_B;
        uint32_t base1 = stB + (uint32_t)((c0 + 1) & 3) * STAGE_B;

        // load ALL fragments of both chunks to registers
        uint32_t a[2][2][4][4], b[2][2][2][4];   // [chunk][ks][mi][4] / [chunk][ks][nh][4]
#pragma unroll
        for (int cc = 0; cc < 2; cc++) {
            uint32_t base = cc ? base1 : base0;
            uint32_t bB = base + A_ST;
#pragma unroll
            for (int ks = 0; ks < 2; ks++) {
                uint32_t ka = (uint32_t)ks * 32;
#pragma unroll
                for (int mi = 0; mi < 4; mi++)
                    ldsm4(a[cc][ks][mi], base + aRowByte + (uint32_t)mi * (16 * ROWB) + ka + aColByte);
                ldsm4(b[cc][ks][0], bB + bRowByte + ka + bColByte);
                ldsm4(b[cc][ks][1], bB + bRowByte + 16u * ROWB + ka + bColByte);
            }
        }
        BARG(barId);                       // all reads done -> stages reusable

        // commit chunks c0+4, c0+5 (land in the two stages just freed)
#pragma unroll
        for (int q = 0; q < 2; q++) {
            int nc = c0 + 4 + q;
            if (nc < NCHUNK) {
                uint32_t nbase = stB + (uint32_t)(nc & 3) * STAGE_B;
#pragma unroll
                for (int i = 0; i < 4; i++) CP16(nbase + aDst[i], aSrc[i] + nc * 32);
#pragma unroll
                for (int i = 0; i < 2; i++) CP16(nbase + bDst[i], bSrc[i] + nc * 32);
                CP_COMMIT();
            }
        }

        // 64 mmas from registers
#pragma unroll
        for (int cc = 0; cc < 2; cc++)
#pragma unroll
            for (int ks = 0; ks < 2; ks++)
#pragma unroll
                for (int mi = 0; mi < 4; mi++)
#pragma unroll
                    for (int ni = 0; ni < 4; ni++)
                        mma16816(acc[mi][ni], a[cc][ks][mi], &b[cc][ks][ni >> 1][(ni & 1) * 2]);
    }

    // -------- reduce the two K-halves through Cs --------
    if (g == 0) {
#pragma unroll
        for (int mi = 0; mi < 4; mi++) {
            int row = wm * 64 + mi * 16 + (lane >> 2);
#pragma unroll
            for (int ni = 0; ni < 4; ni++) {
                int col = wn * 32 + ni * 8 + ((lane & 3) << 1);
                Cs[row][col]     = acc[mi][ni][0];
                Cs[row][col + 1] = acc[mi][ni][1];
                Cs[row + 8][col]     = acc[mi][ni][2];
                Cs[row + 8][col + 1] = acc[mi][ni][3];
            }
        }
    }
    __syncthreads();
    if (g == 1) {
#pragma unroll
        for (int mi = 0; mi < 4; mi++) {
            int row = wm * 64 + mi * 16 + (lane >> 2);
#pragma unroll
            for (int ni = 0; ni < 4; ni++) {
                int col = wn * 32 + ni * 8 + ((lane & 3) << 1);
                Cs[row][col]     += acc[mi][ni][0];
                Cs[row][col + 1] += acc[mi][ni][1];
                Cs[row + 8][col]     += acc[mi][ni][2];
                Cs[row + 8][col + 1] += acc[mi][ni][3];
            }
        }
    }
    __syncthreads();

    // -------- fused pointwise: thread -> 8 hidden units of batch row pm --------
    const int pm = tid & 127;
    const int ph = tid >> 7;             // half (0..1): units ph*8..ph*8+7
    const int pb = pm & 63;
    const int t = (pm < 64) ? s : (T_ - 1 - s);
    const int myLen = lens[pb];
    const float* xg = g_Xg + (size_t)(t * B_ + pb) * G4 + 4 * (j0 + ph * 8);
    float* cptr = g_c + (size_t)pm * H_ + j0 + ph * 8;
    float4 c0v = *(const float4*)(cptr);
    float4 c1v = *(const float4*)(cptr + 4);
    float cst[8] = {c0v.x, c0v.y, c0v.z, c0v.w, c1v.x, c1v.y, c1v.z, c1v.w};

    __half hv8[8];
#pragma unroll
    for (int q = 0; q < 8; q++) {
        int jl = ph * 8 + q, nl = 4 * jl;
        float4 z  = *(const float4*)&Cs[pm][nl];
        float4 x4 = __ldg((const float4*)(xg + 4 * q));
        float zi = z.x + x4.x + sBias[nl + 0];
        float zf = z.y + x4.y + sBias[nl + 1];
        float zg = z.z + x4.z + sBias[nl + 2];
        float zo = z.w + x4.w + sBias[nl + 3];
        float cv = sigm(zf) * cst[q] + sigm(zi) * tanh_f(zg);
        float hv = sigm(zo) * tanh_f(cv);
        cst[q] = cv;
        hv8[q] = __float2half(hv);
        if (pm < 64) {
            if (myLen == s + 1) out[(size_t)pb * (2 * H_) + j0 + jl] = hv;
        } else if (s == T_ - 1) {
            out[(size_t)pb * (2 * H_) + H_ + j0 + jl] = hv;
        }
    }
    *(float4*)(cptr)     = make_float4(cst[0], cst[1], cst[2], cst[3]);
    *(float4*)(cptr + 4) = make_float4(cst[4], cst[5], cst[6], cst[7]);
    *(uint4*)&g_h16[(size_t)pm * H_ + j0 + ph * 8] = *(uint4*)hv8;
}

// ---------------- launch ----------------
extern "C" void kernel_launch(void* const* d_in, const int* in_sizes, int n_in,
                              void* d_out, int out_size)
{
    (void)in_sizes; (void)n_in; (void)out_size;
    const int*   tokens = (const int*)  d_in[0];
    const int*   lens   = (const int*)  d_in[1];
    const float* embed  = (const float*)d_in[2];
    const float* W_ih   = (const float*)d_in[3];
    const float* W_hh   = (const float*)d_in[4];
    const float* b_ih   = (const float*)d_in[5];
    const float* b_hh   = (const float*)d_in[6];
    float* out = (float*)d_out;

    cudaFuncSetAttribute(lstm_step,
                         cudaFuncAttributeMaxDynamicSharedMemorySize, DYN_SMEM);

    void *pA, *pB, *pXg;
    cudaGetSymbolAddress(&pA, g_Acat);
    cudaGetSymbolAddress(&pB, g_Bcat);
    cudaGetSymbolAddress(&pXg, g_Xg);

    prep_all<<<NB_WHH + NB_WIH + NB_X + NB_MISC, 256>>>(
        tokens, embed, W_ih, W_hh, b_ih, b_hh);

    gemm_kernel<<<dim3(G4 / 64, TB / 128), 256>>>(
        (const __half*)pA, (const __half*)pB, (float*)pXg, KCAT, KCAT, G4, KCAT);

    for (int s = 0; s < T_; s++)
        lstm_step<<<NCTA, 256, DYN_SMEM>>>(s, lens, out);
}